// round 15
// baseline (speedup 1.0000x reference)
#include <cuda_runtime.h>
#include <cuda_bf16.h>
#include <cstdint>

#define NROWS   131072
#define D_IN    512
#define DH      128
#define NCODE   256
#define BETA    0.25

// ---------------- scratch ----------------
__device__ __nv_bfloat16  g_wenc[(size_t)DH * D_IN];      // 128 x 512
__device__ __nv_bfloat16  g_wdec[(size_t)D_IN * DH];      // 512 x 128
__device__ __nv_bfloat16  g_cb[3 * NCODE * DH];           // 3 x 256 x 128
__device__ float          g_cn[3 * NCODE];
__device__ double g_rq;
__device__ double g_recon;
__device__ int    g_used[3 * NCODE];

// ---------------- helpers ----------------
__device__ __forceinline__ uint32_t s2u(const void* p) {
    uint32_t a;
    asm("{ .reg .u64 t; cvta.to.shared.u64 t, %1; cvt.u32.u64 %0, t; }" : "=r"(a) : "l"(p));
    return a;
}
__device__ __forceinline__ void ldsm4(uint32_t* r, uint32_t addr) {
    asm volatile("ldmatrix.sync.aligned.m8n8.x4.shared.b16 {%0,%1,%2,%3}, [%4];"
        : "=r"(r[0]), "=r"(r[1]), "=r"(r[2]), "=r"(r[3]) : "r"(addr));
}
__device__ __forceinline__ void mma16816(float* c, const uint32_t* a, const uint32_t* b) {
    asm volatile("mma.sync.aligned.m16n8k16.row.col.f32.bf16.bf16.f32 "
        "{%0,%1,%2,%3}, {%4,%5,%6,%7}, {%8,%9}, {%0,%1,%2,%3};"
        : "+f"(c[0]), "+f"(c[1]), "+f"(c[2]), "+f"(c[3])
        : "r"(a[0]), "r"(a[1]), "r"(a[2]), "r"(a[3]), "r"(b[0]), "r"(b[1]));
}
__device__ __forceinline__ void st_bf2(__nv_bfloat16* p, float a, float b) {
    __nv_bfloat162 v = __floats2bfloat162_rn(a, b);
    *(uint32_t*)p = *(uint32_t*)&v;
}
__device__ __forceinline__ uint32_t pack_bf2(float a, float b) {
    __nv_bfloat162 v = __floats2bfloat162_rn(a, b);
    return *(uint32_t*)&v;
}
__device__ __forceinline__ void cp16(uint32_t dst, const void* src) {
    asm volatile("cp.async.cg.shared.global [%0], [%1], 16;" :: "r"(dst), "l"(src));
}
__device__ __forceinline__ void cp_commit() {
    asm volatile("cp.async.commit_group;" ::: "memory");
}
template<int N> __device__ __forceinline__ void cp_wait() {
    asm volatile("cp.async.wait_group %0;" :: "n"(N) : "memory");
}
__device__ __forceinline__ void l2_prefetch(const void* p) {
    asm volatile("prefetch.global.L2 [%0];" :: "l"(p));
}

// ---------------- init / norms / convert ----------------
__global__ void k_init() {
    int t = threadIdx.x;
    if (t == 0) { g_rq = 0.0; g_recon = 0.0; }
    if (t < 3 * NCODE) g_used[t] = 0;
}
__global__ void k_norms(const float* __restrict__ cb0,
                        const float* __restrict__ cb1,
                        const float* __restrict__ cb2) {
    const float* cbs[3] = {cb0, cb1, cb2};
    const float* cb = cbs[blockIdx.x];
    int t = threadIdx.x;
    float s = 0.f;
#pragma unroll
    for (int q = 0; q < 32; q++) {
        float4 v = *(const float4*)(cb + (size_t)t * DH + q * 4);
        s += v.x * v.x + v.y * v.y + v.z * v.z + v.w * v.w;
    }
    g_cn[blockIdx.x * NCODE + t] = s;
}
__global__ void k_cvt(const float* __restrict__ we, const float* __restrict__ wd,
                      const float* __restrict__ c0, const float* __restrict__ c1,
                      const float* __restrict__ c2) {
    int i = blockIdx.x * 256 + threadIdx.x;
    const float* src; uint32_t* dst; int off;
    if (i < 32768)       { src = we; dst = (uint32_t*)g_wenc;         off = i; }
    else if (i < 65536)  { src = wd; dst = (uint32_t*)g_wdec;         off = i - 32768; }
    else if (i < 81920)  { src = c0; dst = (uint32_t*)g_cb;           off = i - 65536; }
    else if (i < 98304)  { src = c1; dst = (uint32_t*)g_cb + 16384;   off = i - 81920; }
    else                 { src = c2; dst = (uint32_t*)g_cb + 32768;   off = i - 98304; }
    float2 v = ((const float2*)src)[off];
    __nv_bfloat162 p = __floats2bfloat162_rn(v.x, v.y);
    dst[off] = *(uint32_t*)&p;
}

// =========================================================================
// Fused kernel, 128 rows/CTA, 256 thr (2 row-groups x 4 col-groups),
// warp tile 64x32, 2 CTAs/SM. One barrier per pipeline iteration.
// =========================================================================
#define F_SA   0
#define F_RG   34816
#define F_BV   108544
#define F_BI   110592
#define F_IDX  112640
#define F_SMEM 113664

__global__ __launch_bounds__(256, 2) void k_fused(const float* __restrict__ emb,
                                                  const float* __restrict__ cb0,
                                                  const float* __restrict__ cb1,
                                                  const float* __restrict__ cb2) {
    extern __shared__ char smc[];
    __nv_bfloat16* sA = (__nv_bfloat16*)(smc + F_SA);
    float* bestv = (float*)(smc + F_BV);
    int*   besti = (int*)(smc + F_BI);
    int*   idx01 = (int*)(smc + F_IDX);
    uint32_t aBase = s2u(smc);
    uint32_t aSA = aBase + F_SA, aRG = aBase + F_RG;
    uint32_t aE[2] = {aRG, aRG + 18432};
    uint32_t aW[2] = {aRG + 36864, aRG + 55296};
    uint32_t aCBB[2] = {aRG, aRG + 36864};

    int t = threadIdx.x, lane = t & 31, wid = t >> 5;
    int wr = wid >> 2, wc = wid & 3;
    int row0 = blockIdx.x * 128;

    // ---- pre-loop: wenc chunk0, emb chunk0 regs + stage, emb chunk1 regs ----
#pragma unroll
    for (int i = 0; i < 4; i++) {
        int q = i * 256 + t;
        int row = q >> 3, c16 = q & 7;
        cp16(aW[0] + row * 144 + c16 * 16, g_wenc + (size_t)row * D_IN + c16 * 8);
    }
    cp_commit();

    float4 pe4[4][2];
#pragma unroll
    for (int i = 0; i < 4; i++) {
        int s = i * 256 + t;
        int row = s >> 3, cb8 = s & 7;
        const float* p = emb + (size_t)(row0 + row) * D_IN + cb8 * 8;
        pe4[i][0] = *(const float4*)p;
        pe4[i][1] = *(const float4*)(p + 4);
    }
#pragma unroll
    for (int i = 0; i < 4; i++) {
        int s = i * 256 + t;
        int row = s >> 3, cb8 = s & 7;
        uint4 u;
        u.x = pack_bf2(pe4[i][0].x, pe4[i][0].y);
        u.y = pack_bf2(pe4[i][0].z, pe4[i][0].w);
        u.z = pack_bf2(pe4[i][1].x, pe4[i][1].y);
        u.w = pack_bf2(pe4[i][1].z, pe4[i][1].w);
        *(uint4*)(smc + F_RG + row * 144 + cb8 * 16) = u;
    }
#pragma unroll
    for (int i = 0; i < 4; i++) {
        int s = i * 256 + t;
        int row = s >> 3, cb8 = s & 7;
        const float* p = emb + (size_t)(row0 + row) * D_IN + 64 + cb8 * 8;
        pe4[i][0] = *(const float4*)p;
        pe4[i][1] = *(const float4*)(p + 4);
    }

    // =========== Phase 1: latent = emb @ Wenc^T ===========
    float acc1[4][4][4];
#pragma unroll
    for (int mt = 0; mt < 4; mt++)
#pragma unroll
        for (int nt = 0; nt < 4; nt++)
#pragma unroll
            for (int j = 0; j < 4; j++) acc1[mt][nt][j] = 0.f;

    for (int c = 0; c < 8; c++) {
        cp_wait<0>();
        __syncthreads();
        if (c < 7) {
#pragma unroll
            for (int i = 0; i < 4; i++) {
                int q = i * 256 + t;
                int row = q >> 3, c16 = q & 7;
                cp16(aW[(c + 1) & 1] + row * 144 + c16 * 16,
                     g_wenc + (size_t)row * D_IN + (c + 1) * 64 + c16 * 8);
            }
            cp_commit();
#pragma unroll
            for (int i = 0; i < 4; i++) {
                int s = i * 256 + t;
                int row = s >> 3, cb8 = s & 7;
                uint4 u;
                u.x = pack_bf2(pe4[i][0].x, pe4[i][0].y);
                u.y = pack_bf2(pe4[i][0].z, pe4[i][0].w);
                u.z = pack_bf2(pe4[i][1].x, pe4[i][1].y);
                u.w = pack_bf2(pe4[i][1].z, pe4[i][1].w);
                *(uint4*)(smc + F_RG + ((c + 1) & 1) * 18432 + row * 144 + cb8 * 16) = u;
            }
        }
        if (c < 6) {
#pragma unroll
            for (int i = 0; i < 4; i++) {
                int s = i * 256 + t;
                int row = s >> 3, cb8 = s & 7;
                const float* p = emb + (size_t)(row0 + row) * D_IN + (c + 2) * 64 + cb8 * 8;
                pe4[i][0] = *(const float4*)p;
                pe4[i][1] = *(const float4*)(p + 4);
            }
        }
        uint32_t aEc = aE[c & 1], aWc = aW[c & 1];
#pragma unroll
        for (int kt = 0; kt < 4; kt++) {
            uint32_t af[4][4], bfr[2][4];
#pragma unroll
            for (int mt = 0; mt < 4; mt++)
                ldsm4(af[mt], aEc + ((wr * 64 + mt * 16 + (lane & 15)) * 72
                                     + kt * 16 + (lane >> 4) * 8) * 2);
#pragma unroll
            for (int np = 0; np < 2; np++) {
                int n = wc * 32 + np * 16 + (lane & 7) + ((lane >> 4) & 1) * 8;
                ldsm4(bfr[np], aWc + (n * 72 + kt * 16 + ((lane >> 3) & 1) * 8) * 2);
            }
#pragma unroll
            for (int mt = 0; mt < 4; mt++)
#pragma unroll
                for (int np = 0; np < 2; np++) {
                    mma16816(acc1[mt][2 * np],     af[mt], &bfr[np][0]);
                    mma16816(acc1[mt][2 * np + 1], af[mt], &bfr[np][2]);
                }
        }
    }
    __syncthreads();
#pragma unroll
    for (int mt = 0; mt < 4; mt++)
#pragma unroll
        for (int nt = 0; nt < 4; nt++) {
            int row = wr * 64 + mt * 16 + (lane >> 2);
            int col = wc * 32 + nt * 8 + (lane & 3) * 2;
            st_bf2(&sA[row * 136 + col],       acc1[mt][nt][0], acc1[mt][nt][1]);
            st_bf2(&sA[(row + 8) * 136 + col], acc1[mt][nt][2], acc1[mt][nt][3]);
        }
#pragma unroll
    for (int i = 0; i < 8; i++) {
        int q = i * 256 + t;
        int row = q >> 4, c16 = q & 15;
        cp16(aCBB[0] + row * 272 + c16 * 16, g_cb + (size_t)row * DH + c16 * 8);
    }
    cp_commit();

    // =========== Phase 2: 3-level RQ, 128-code slabs ===========
    float rql = 0.f;
    const float* cbs[3] = {cb0, cb1, cb2};
    float best[8]; int bidx[8];

    for (int j = 0; j < 6; j++) {
        int L = j >> 1, h = j & 1;
        uint32_t aCBc = aCBB[j & 1];
        cp_wait<0>();
        __syncthreads();
        if (j < 5) {
#pragma unroll
            for (int i = 0; i < 8; i++) {
                int q = i * 256 + t;
                int row = q >> 4, c16 = q & 15;
                cp16(aCBB[(j + 1) & 1] + row * 272 + c16 * 16,
                     g_cb + (size_t)((j + 1) >> 1) * NCODE * DH
                          + (size_t)(((j + 1) & 1) * 128 + row) * DH + c16 * 8);
            }
            cp_commit();
        } else {
#pragma unroll
            for (int i = 0; i < 8; i++) {
                int q = i * 256 + t;
                int row = q >> 4, c16 = q & 15;
                cp16(aCBB[0] + row * 272 + c16 * 16, g_wdec + (size_t)row * DH + c16 * 8);
            }
            cp_commit();
        }
        if (j == 4) {
            // L2-prefetch this CTA's phase-3 emb tile (2048 x 128B lines)
#pragma unroll
            for (int i = 0; i < 8; i++) {
                int l = t * 8 + i;
                const char* p = (const char*)(emb + (size_t)(row0 + (l >> 4)) * D_IN)
                              + (size_t)(l & 15) * 128;
                l2_prefetch(p);
            }
        }
        if (h == 0) {
#pragma unroll
            for (int s = 0; s < 8; s++) { best[s] = 3.4e38f; bidx[s] = 0; }
        }
        float2 cnv[4];
#pragma unroll
        for (int nt = 0; nt < 4; nt++)
            cnv[nt] = *(const float2*)(g_cn + L * NCODE + h * 128 + wc * 32
                                       + nt * 8 + (lane & 3) * 2);

        float acc[4][4][4];
#pragma unroll
        for (int mt = 0; mt < 4; mt++)
#pragma unroll
            for (int nt = 0; nt < 4; nt++)
#pragma unroll
                for (int q = 0; q < 4; q++) acc[mt][nt][q] = 0.f;
#pragma unroll
        for (int kt = 0; kt < 8; kt++) {
            uint32_t af[4][4], bfr[2][4];
#pragma unroll
            for (int mt = 0; mt < 4; mt++)
                ldsm4(af[mt], aSA + ((wr * 64 + mt * 16 + (lane & 15)) * 136
                                     + kt * 16 + (lane >> 4) * 8) * 2);
#pragma unroll
            for (int np = 0; np < 2; np++) {
                int n = wc * 32 + np * 16 + (lane & 7) + ((lane >> 4) & 1) * 8;
                ldsm4(bfr[np], aCBc + (n * 136 + kt * 16 + ((lane >> 3) & 1) * 8) * 2);
            }
#pragma unroll
            for (int mt = 0; mt < 4; mt++)
#pragma unroll
                for (int np = 0; np < 2; np++) {
                    mma16816(acc[mt][2 * np],     af[mt], &bfr[np][0]);
                    mma16816(acc[mt][2 * np + 1], af[mt], &bfr[np][2]);
                }
        }
#pragma unroll
        for (int mt = 0; mt < 4; mt++)
#pragma unroll
            for (int nt = 0; nt < 4; nt++) {
                int col = h * 128 + wc * 32 + nt * 8 + (lane & 3) * 2;
#pragma unroll
                for (int hi = 0; hi < 2; hi++) {
                    int s = mt * 2 + hi;
                    float k0 = fmaf(-2.f, acc[mt][nt][hi * 2],     cnv[nt].x);
                    float k1 = fmaf(-2.f, acc[mt][nt][hi * 2 + 1], cnv[nt].y);
                    if (k0 < best[s]) { best[s] = k0; bidx[s] = col; }
                    if (k1 < best[s]) { best[s] = k1; bidx[s] = col + 1; }
                }
            }

        if (h == 1) {
            const float* cbg = cbs[L];
#pragma unroll
            for (int s = 0; s < 8; s++) {
                float bv = best[s]; int bi = bidx[s];
#pragma unroll
                for (int off = 1; off < 4; off <<= 1) {
                    float ov = __shfl_xor_sync(0xffffffffu, bv, off);
                    int   oi = __shfl_xor_sync(0xffffffffu, bi, off);
                    if (ov < bv || (ov == bv && oi < bi)) { bv = ov; bi = oi; }
                }
                if ((lane & 3) == 0) {
                    int row = wr * 64 + (s >> 1) * 16 + (s & 1) * 8 + (lane >> 2);
                    bestv[wc * 128 + row] = bv;
                    besti[wc * 128 + row] = bi;
                }
            }
            __syncthreads();
            // fused cross-warp argmin + remainder/restored update (single barrier)
#pragma unroll
            for (int i = 0; i < 16; i++) {
                int r = wid * 16 + i;
                float bv = bestv[r]; int ci = besti[r];
#pragma unroll
                for (int w = 1; w < 4; w++) {
                    float ov = bestv[w * 128 + r]; int oi = besti[w * 128 + r];
                    if (ov < bv || (ov == bv && oi < ci)) { bv = ov; ci = oi; }
                }
                if (lane == 0) {
                    g_used[L * NCODE + ci] = 1;
                    if (L < 2) idx01[L * 128 + r] = ci;
                }
                float4 cv = *(const float4*)(cbg + (size_t)ci * DH + lane * 4);
                uint32_t p0 = *(uint32_t*)&sA[r * 136 + lane * 4];
                uint32_t p1 = *(uint32_t*)&sA[r * 136 + lane * 4 + 2];
                __nv_bfloat162 b0 = *(__nv_bfloat162*)&p0;
                __nv_bfloat162 b1 = *(__nv_bfloat162*)&p1;
                float n0 = __low2float(b0)  - cv.x;
                float n1 = __high2float(b0) - cv.y;
                float n2 = __low2float(b1)  - cv.z;
                float n3 = __high2float(b1) - cv.w;
                rql += n0 * n0 + n1 * n1 + n2 * n2 + n3 * n3;
                if (L < 2) {
                    st_bf2(&sA[r * 136 + lane * 4],     n0, n1);
                    st_bf2(&sA[r * 136 + lane * 4 + 2], n2, n3);
                } else {
                    int i0 = idx01[r], i1 = idx01[128 + r];
                    float4 a0 = *(const float4*)(cb0 + (size_t)i0 * DH + lane * 4);
                    float4 a1 = *(const float4*)(cb1 + (size_t)i1 * DH + lane * 4);
                    st_bf2(&sA[r * 136 + lane * 4],
                           a0.x + a1.x + cv.x, a0.y + a1.y + cv.y);
                    st_bf2(&sA[r * 136 + lane * 4 + 2],
                           a0.z + a1.z + cv.z, a0.w + a1.w + cv.w);
                }
            }
        }
    }

    // =========== Phase 3: recon GEMM + fused MSE (4 passes of 128 N) =======
    float local = 0.f;
    for (int p = 0; p < 4; p++) {
        uint32_t aDc = aCBB[p & 1];
        cp_wait<0>();
        __syncthreads();
        if (p < 3) {
#pragma unroll
            for (int i = 0; i < 8; i++) {
                int q = i * 256 + t;
                int row = q >> 4, c16 = q & 15;
                cp16(aCBB[(p + 1) & 1] + row * 272 + c16 * 16,
                     g_wdec + (size_t)((p + 1) * 128 + row) * DH + c16 * 8);
            }
            cp_commit();
        }
        float accR[4][4][4];
#pragma unroll
        for (int mt = 0; mt < 4; mt++)
#pragma unroll
            for (int nt = 0; nt < 4; nt++)
#pragma unroll
                for (int q = 0; q < 4; q++) accR[mt][nt][q] = 0.f;
#pragma unroll
        for (int kt = 0; kt < 8; kt++) {
            uint32_t af[4][4], bfr[2][4];
#pragma unroll
            for (int mt = 0; mt < 4; mt++)
                ldsm4(af[mt], aSA + ((wr * 64 + mt * 16 + (lane & 15)) * 136
                                     + kt * 16 + (lane >> 4) * 8) * 2);
#pragma unroll
            for (int np = 0; np < 2; np++) {
                int n = wc * 32 + np * 16 + (lane & 7) + ((lane >> 4) & 1) * 8;
                ldsm4(bfr[np], aDc + (n * 136 + kt * 16 + ((lane >> 3) & 1) * 8) * 2);
            }
#pragma unroll
            for (int mt = 0; mt < 4; mt++)
#pragma unroll
                for (int np = 0; np < 2; np++) {
                    mma16816(accR[mt][2 * np],     af[mt], &bfr[np][0]);
                    mma16816(accR[mt][2 * np + 1], af[mt], &bfr[np][2]);
                }
        }
#pragma unroll
        for (int mt = 0; mt < 4; mt++)
#pragma unroll
            for (int nt = 0; nt < 4; nt++) {
                int row = row0 + wr * 64 + mt * 16 + (lane >> 2);
                int col = p * 128 + wc * 32 + nt * 8 + (lane & 3) * 2;
                float2 e0 = *(const float2*)(emb + (size_t)row * D_IN + col);
                float2 e1 = *(const float2*)(emb + (size_t)(row + 8) * D_IN + col);
                float d0 = accR[mt][nt][0] - e0.x;
                float d1 = accR[mt][nt][1] - e0.y;
                float d2 = accR[mt][nt][2] - e1.x;
                float d3 = accR[mt][nt][3] - e1.y;
                local += d0 * d0 + d1 * d1 + d2 * d2 + d3 * d3;
            }
    }

    // ---- reductions ----
#pragma unroll
    for (int off = 16; off > 0; off >>= 1) {
        rql   += __shfl_xor_sync(0xffffffffu, rql, off);
        local += __shfl_xor_sync(0xffffffffu, local, off);
    }
    if (lane == 0) {
        atomicAdd(&g_rq, (double)rql);
        atomicAdd(&g_recon, (double)local);
    }
}

// ---------------- finalize ----------------
__global__ void k_finalize(float* __restrict__ out, int out_size) {
    __shared__ int cnt[3];
    int t = threadIdx.x;
    if (t < 3) cnt[t] = 0;
    __syncthreads();
    if (t < 3 * NCODE) { if (g_used[t]) atomicAdd(&cnt[t / NCODE], 1); }
    __syncthreads();
    if (t == 0) {
        double recon = g_recon / ((double)NROWS * (double)D_IN);
        double rq    = (1.0 + BETA) * g_rq / ((double)NROWS * (double)DH);
        float rf = (float)recon, qf = (float)rq;
        if (out_size > 0) out[0] = rf + qf;
        if (out_size > 1) out[1] = rf;
        if (out_size > 2) out[2] = qf;
        if (out_size > 3) out[3] = (float)cnt[0];
        if (out_size > 4) out[4] = (float)cnt[1];
        if (out_size > 5) out[5] = (float)cnt[2];
    }
    for (int i = 6 + t; i < out_size; i += blockDim.x) out[i] = 0.f;
}

// ---------------- launch ----------------
extern "C" void kernel_launch(void* const* d_in, const int* in_sizes, int n_in,
                              void* d_out, int out_size) {
    const float* emb  = (const float*)d_in[0];
    const float* Wenc = (const float*)d_in[1];
    const float* Wdec = (const float*)d_in[2];
    const float* cb0  = (const float*)d_in[3];
    const float* cb1  = (const float*)d_in[4];
    const float* cb2  = (const float*)d_in[5];

    cudaFuncSetAttribute(k_fused, cudaFuncAttributeMaxDynamicSharedMemorySize, F_SMEM);

    k_init<<<1, 768>>>();
    k_norms<<<3, 256>>>(cb0, cb1, cb2);
    k_cvt<<<448, 256>>>(Wenc, Wdec, cb0, cb1, cb2);
    k_fused<<<NROWS / 128, 256, F_SMEM>>>(emb, cb0, cb1, cb2);
    k_finalize<<<1, 768>>>((float*)d_out, out_size);
}

// round 16
// speedup vs baseline: 1.0601x; 1.0601x over previous
#include <cuda_runtime.h>
#include <cuda_bf16.h>
#include <cstdint>

#define NROWS   131072
#define D_IN    512
#define DH      128
#define NCODE   256
#define BETA    0.25

// ---------------- scratch ----------------
__device__ __nv_bfloat16  g_wcomb[(size_t)2 * DH * D_IN];  // [256][512]: rows 0-127 Wenc, 128-255 Wdec^T
__device__ __nv_bfloat16  g_cb[3 * NCODE * DH];            // bf16 codebooks
__device__ __nv_bfloat16  g_G[2 * DH * DH];                // Gram split: hi, lo
__device__ float          g_cn[3 * NCODE];
__device__ double g_rq;
__device__ double g_recon;
__device__ int    g_used[3 * NCODE];

// ---------------- helpers ----------------
__device__ __forceinline__ uint32_t s2u(const void* p) {
    uint32_t a;
    asm("{ .reg .u64 t; cvta.to.shared.u64 t, %1; cvt.u32.u64 %0, t; }" : "=r"(a) : "l"(p));
    return a;
}
__device__ __forceinline__ void ldsm4(uint32_t* r, uint32_t addr) {
    asm volatile("ldmatrix.sync.aligned.m8n8.x4.shared.b16 {%0,%1,%2,%3}, [%4];"
        : "=r"(r[0]), "=r"(r[1]), "=r"(r[2]), "=r"(r[3]) : "r"(addr));
}
__device__ __forceinline__ void mma16816(float* c, const uint32_t* a, const uint32_t* b) {
    asm volatile("mma.sync.aligned.m16n8k16.row.col.f32.bf16.bf16.f32 "
        "{%0,%1,%2,%3}, {%4,%5,%6,%7}, {%8,%9}, {%0,%1,%2,%3};"
        : "+f"(c[0]), "+f"(c[1]), "+f"(c[2]), "+f"(c[3])
        : "r"(a[0]), "r"(a[1]), "r"(a[2]), "r"(a[3]), "r"(b[0]), "r"(b[1]));
}
__device__ __forceinline__ void st_bf2(__nv_bfloat16* p, float a, float b) {
    __nv_bfloat162 v = __floats2bfloat162_rn(a, b);
    *(uint32_t*)p = *(uint32_t*)&v;
}
__device__ __forceinline__ uint32_t pack_bf2(float a, float b) {
    __nv_bfloat162 v = __floats2bfloat162_rn(a, b);
    return *(uint32_t*)&v;
}
__device__ __forceinline__ void bf2f(uint32_t u, float& a, float& b) {
    __nv_bfloat162 v = *(__nv_bfloat162*)&u;
    a = __low2float(v); b = __high2float(v);
}
__device__ __forceinline__ void cp16(uint32_t dst, const void* src) {
    asm volatile("cp.async.cg.shared.global [%0], [%1], 16;" :: "r"(dst), "l"(src));
}
__device__ __forceinline__ void cp_commit() {
    asm volatile("cp.async.commit_group;" ::: "memory");
}
template<int N> __device__ __forceinline__ void cp_wait() {
    asm volatile("cp.async.wait_group %0;" :: "n"(N) : "memory");
}

// ---------------- setup kernels ----------------
__global__ void k_init() {
    int t = threadIdx.x;
    if (t == 0) { g_rq = 0.0; g_recon = 0.0; }
    if (t < 3 * NCODE) g_used[t] = 0;
}
__global__ void k_norms(const float* __restrict__ cb0,
                        const float* __restrict__ cb1,
                        const float* __restrict__ cb2) {
    const float* cbs[3] = {cb0, cb1, cb2};
    const float* cb = cbs[blockIdx.x];
    int t = threadIdx.x;
    float s = 0.f;
#pragma unroll
    for (int q = 0; q < 32; q++) {
        float4 v = *(const float4*)(cb + (size_t)t * DH + q * 4);
        s += v.x * v.x + v.y * v.y + v.z * v.z + v.w * v.w;
    }
    g_cn[blockIdx.x * NCODE + t] = s;
}
// wenc -> wcomb[0:128], wdec^T -> wcomb[128:256], codebooks -> bf16
__global__ void k_cvt(const float* __restrict__ we, const float* __restrict__ wd,
                      const float* __restrict__ c0, const float* __restrict__ c1,
                      const float* __restrict__ c2) {
    int i = blockIdx.x * 256 + threadIdx.x;
    if (i < 32768) {
        float2 v = ((const float2*)we)[i];
        ((uint32_t*)g_wcomb)[i] = pack_bf2(v.x, v.y);
    } else if (i < 65536) {
        int j = i - 32768;                 // [128 h][256 kpair]
        int h = j >> 8, kp = j & 255;
        float a = wd[(size_t)(kp * 2) * DH + h];
        float b = wd[(size_t)(kp * 2 + 1) * DH + h];
        ((uint32_t*)g_wcomb)[(size_t)(128 + h) * 256 + kp] = pack_bf2(a, b);
    } else if (i < 114688) {
        int j = i - 65536;
        const float* src = (j < 16384) ? c0 : (j < 32768) ? c1 : c2;
        int off = j & 16383;
        float2 v = ((const float2*)src)[off];
        ((uint32_t*)g_cb)[(j >> 14) * 16384 + off] = pack_bf2(v.x, v.y);
    }
}
// G = Wdec^T Wdec  (sum over 512 rows), split bf16 hi/lo
__global__ void k_gram(const float* __restrict__ wd) {
    __shared__ float col[512];
    int i = blockIdx.x, t = threadIdx.x;
    for (int k = t; k < 512; k += 128) col[k] = wd[(size_t)k * DH + i];
    __syncthreads();
    float s = 0.f;
    for (int k = 0; k < 512; k++) s += col[k] * wd[(size_t)k * DH + t];
    __nv_bfloat16 hi = __float2bfloat16(s);
    float lo = s - __bfloat162float(hi);
    g_G[i * DH + t] = hi;
    g_G[DH * DH + i * DH + t] = __float2bfloat16(lo);
}

// =========================================================================
// Fused kernel: 128 rows/CTA, 512 thr (4x4 warp grid, warp tile 32xN).
// Phase1: [latent|U] = emb @ [Wenc;WdecT]^T (N=256, 16 chunks of K=32)
// Phase2: 3 levels, full-codebook N=256 GEMMs (cb resident/ping-pong)
// Final:  rGr^T via restored@G(hi+lo) + dot(restored,U) + Sum emb^2
// smem:
//  sA  @0      34816 (rem->restored bf16 128x136)
//  sU  @34816  34816 (U bf16 128x136)
//  CB0 @69632  69632 (cb0, then cb2)
//  CB1 @139264 69632 (phase1 B dbl-buf 2x20480, then cb1, then G hi/lo)
//  EB  @208896 10240 (emb chunk 128x80B)
//  BV  @219136 2048 | BI @221184 2048 | IDX @223232 1024
// total 224256
// =========================================================================
#define F_SA   0
#define F_SU   34816
#define F_CB0  69632
#define F_CB1  139264
#define F_EB   208896
#define F_BV   219136
#define F_BI   221184
#define F_IDX  223232
#define F_SMEM 224256

__global__ __launch_bounds__(512, 1) void k_fused(const float* __restrict__ emb,
                                                  const float* __restrict__ cb0,
                                                  const float* __restrict__ cb1,
                                                  const float* __restrict__ cb2) {
    extern __shared__ char smc[];
    __nv_bfloat16* sA = (__nv_bfloat16*)(smc + F_SA);
    __nv_bfloat16* sU = (__nv_bfloat16*)(smc + F_SU);
    float* bestv = (float*)(smc + F_BV);
    int*   besti = (int*)(smc + F_BI);
    int*   idx01 = (int*)(smc + F_IDX);
    uint32_t aBase = s2u(smc);
    uint32_t aSA = aBase + F_SA;
    uint32_t aCB0 = aBase + F_CB0, aCB1 = aBase + F_CB1, aEB = aBase + F_EB;

    int t = threadIdx.x, lane = t & 31, wid = t >> 5;
    int wr = wid >> 2, wc = wid & 3;        // 4 row-groups x 4 col-groups
    int row0 = blockIdx.x * 128;

    float se2 = 0.f;

    // ---- pre-loop: B chunk 0 (+cb0 part 0), pe4 chunk 0 ----
#pragma unroll
    for (int i = 0; i < 2; i++) {           // B chunk 0 -> CB1 buf 0
        int g = i * 512 + t;
        int row = g >> 2, c16 = g & 3;
        cp16(aCB1 + row * 80 + c16 * 16, g_wcomb + (size_t)row * D_IN + c16 * 8);
    }
    {                                       // cb0 part 0
        int g = t;
        int row = g >> 4, c16 = g & 15;
        cp16(aCB0 + row * 272 + c16 * 16, g_cb + (size_t)row * DH + c16 * 8);
    }
    cp_commit();

    float4 pe4[2];
#pragma unroll
    for (int i = 0; i < 2; i++) {
        int g = i * 512 + t;
        int row = g >> 3, f4 = g & 7;
        pe4[i] = *(const float4*)(emb + (size_t)(row0 + row) * D_IN + f4 * 4);
    }

    // =========== Phase 1 ===========
    float acc1[2][8][4];
#pragma unroll
    for (int mt = 0; mt < 2; mt++)
#pragma unroll
        for (int nt = 0; nt < 8; nt++)
#pragma unroll
            for (int q = 0; q < 4; q++) acc1[mt][nt][q] = 0.f;

    for (int c = 0; c < 16; c++) {
        cp_wait<0>();
        __syncthreads();          // B_c visible; prev MMA done with EB
        // stage emb chunk c from pe4 + sum squares
#pragma unroll
        for (int i = 0; i < 2; i++) {
            int g = i * 512 + t;
            int row = g >> 3, f4 = g & 7;
            uint2 u;
            u.x = pack_bf2(pe4[i].x, pe4[i].y);
            u.y = pack_bf2(pe4[i].z, pe4[i].w);
            *(uint2*)(smc + F_EB + row * 80 + f4 * 8) = u;
            se2 += pe4[i].x * pe4[i].x + pe4[i].y * pe4[i].y
                 + pe4[i].z * pe4[i].z + pe4[i].w * pe4[i].w;
        }
        if (c < 15) {
            // prefetch pe4 chunk c+1
#pragma unroll
            for (int i = 0; i < 2; i++) {
                int g = i * 512 + t;
                int row = g >> 3, f4 = g & 7;
                pe4[i] = *(const float4*)(emb + (size_t)(row0 + row) * D_IN
                                          + (c + 1) * 32 + f4 * 4);
            }
            // issue B chunk c+1 (+cb0 part c+1 while parts remain)
#pragma unroll
            for (int i = 0; i < 2; i++) {
                int g = i * 512 + t;
                int row = g >> 2, c16 = g & 3;
                cp16(aCB1 + ((c + 1) & 1) * 20480 + row * 80 + c16 * 16,
                     g_wcomb + (size_t)row * D_IN + (c + 1) * 32 + c16 * 8);
            }
            if (c + 1 < 8) {
                int g = (c + 1) * 512 + t;
                int row = g >> 4, c16 = g & 15;
                cp16(aCB0 + row * 272 + c16 * 16, g_cb + (size_t)row * DH + c16 * 8);
            }
            cp_commit();
        }
        __syncthreads();          // EB staged
        uint32_t aB = aCB1 + (c & 1) * 20480;
#pragma unroll
        for (int kt = 0; kt < 2; kt++) {
            uint32_t af[2][4], bfr[4][4];
#pragma unroll
            for (int mt = 0; mt < 2; mt++)
                ldsm4(af[mt], aEB + (wr * 32 + mt * 16 + (lane & 15)) * 80
                              + kt * 32 + (lane >> 4) * 16);
#pragma unroll
            for (int np = 0; np < 4; np++) {
                int n = wc * 64 + np * 16 + (lane & 7) + ((lane >> 4) & 1) * 8;
                ldsm4(bfr[np], aB + n * 80 + kt * 32 + ((lane >> 3) & 1) * 16);
            }
#pragma unroll
            for (int mt = 0; mt < 2; mt++)
#pragma unroll
                for (int np = 0; np < 4; np++) {
                    mma16816(acc1[mt][2 * np],     af[mt], &bfr[np][0]);
                    mma16816(acc1[mt][2 * np + 1], af[mt], &bfr[np][2]);
                }
        }
    }
    __syncthreads();
    // store latent -> sA (wc<2), U -> sU (wc>=2)
#pragma unroll
    for (int mt = 0; mt < 2; mt++)
#pragma unroll
        for (int nt = 0; nt < 8; nt++) {
            int row = wr * 32 + mt * 16 + (lane >> 2);
            int colg = wc * 64 + nt * 8 + (lane & 3) * 2;
            __nv_bfloat16* dst = (colg < 128) ? sA : sU;
            int col = colg & 127;
            st_bf2(&dst[row * 136 + col],       acc1[mt][nt][0], acc1[mt][nt][1]);
            st_bf2(&dst[(row + 8) * 136 + col], acc1[mt][nt][2], acc1[mt][nt][3]);
        }
    // issue cb1 -> CB1 (phase-1 B staging dead)
#pragma unroll
    for (int i = 0; i < 8; i++) {
        int g = i * 512 + t;
        int row = g >> 4, c16 = g & 15;
        cp16(aCB1 + row * 272 + c16 * 16,
             g_cb + (size_t)(NCODE + row) * DH + c16 * 8);
    }
    cp_commit();
    __syncthreads();              // sA/sU visible

    // =========== Phase 2: 3 levels, N=256 each ===========
    float rql = 0.f;
    const float* cbs[3] = {cb0, cb1, cb2};

    for (int L = 0; L < 3; L++) {
        if (L > 0) { cp_wait<1>(); __syncthreads(); }   // cb_L ready (older group)
        uint32_t cbBase = (L == 1) ? aCB1 : aCB0;

        float acc[2][8][4];
#pragma unroll
        for (int mt = 0; mt < 2; mt++)
#pragma unroll
            for (int nt = 0; nt < 8; nt++)
#pragma unroll
                for (int q = 0; q < 4; q++) acc[mt][nt][q] = 0.f;
#pragma unroll
        for (int kt = 0; kt < 8; kt++) {
            uint32_t af[2][4], bfr[4][4];
#pragma unroll
            for (int mt = 0; mt < 2; mt++)
                ldsm4(af[mt], aSA + (wr * 32 + mt * 16 + (lane & 15)) * 272
                              + kt * 32 + (lane >> 4) * 16);
#pragma unroll
            for (int np = 0; np < 4; np++) {
                int n = wc * 64 + np * 16 + (lane & 7) + ((lane >> 4) & 1) * 8;
                ldsm4(bfr[np], cbBase + n * 272 + kt * 32 + ((lane >> 3) & 1) * 16);
            }
#pragma unroll
            for (int mt = 0; mt < 2; mt++)
#pragma unroll
                for (int np = 0; np < 4; np++) {
                    mma16816(acc[mt][2 * np],     af[mt], &bfr[np][0]);
                    mma16816(acc[mt][2 * np + 1], af[mt], &bfr[np][2]);
                }
        }
        // code norms + per-thread argmin
        float best[4]; int bidx[4];
#pragma unroll
        for (int s = 0; s < 4; s++) { best[s] = 3.4e38f; bidx[s] = 0; }
#pragma unroll
        for (int nt = 0; nt < 8; nt++) {
            int col = wc * 64 + nt * 8 + (lane & 3) * 2;
            float2 cn = *(const float2*)(g_cn + L * NCODE + col);
#pragma unroll
            for (int hi = 0; hi < 2; hi++) {
                int s = (hi << 1);              // slot = mt*2+hi -> iterate mt below
#pragma unroll
                for (int mt = 0; mt < 2; mt++) {
                    int sl = mt * 2 + hi;
                    float k0 = fmaf(-2.f, acc[mt][nt][hi * 2],     cn.x);
                    float k1 = fmaf(-2.f, acc[mt][nt][hi * 2 + 1], cn.y);
                    if (k0 < best[sl]) { best[sl] = k0; bidx[sl] = col; }
                    if (k1 < best[sl]) { best[sl] = k1; bidx[sl] = col + 1; }
                }
                (void)s;
            }
        }
#pragma unroll
        for (int s = 0; s < 4; s++) {
            float bv = best[s]; int bi = bidx[s];
#pragma unroll
            for (int off = 1; off < 4; off <<= 1) {
                float ov = __shfl_xor_sync(0xffffffffu, bv, off);
                int   oi = __shfl_xor_sync(0xffffffffu, bi, off);
                if (ov < bv || (ov == bv && oi < bi)) { bv = ov; bi = oi; }
            }
            if ((lane & 3) == 0) {
                int row = wr * 32 + (s >> 1) * 16 + (s & 1) * 8 + (lane >> 2);
                bestv[wc * 128 + row] = bv;
                besti[wc * 128 + row] = bi;
            }
        }
        __syncthreads();          // bestv ready; all MMA reads of cb region done
        if (L == 0) {             // cb2 -> CB0
#pragma unroll
            for (int i = 0; i < 8; i++) {
                int g = i * 512 + t;
                int row = g >> 4, c16 = g & 15;
                cp16(aCB0 + row * 272 + c16 * 16,
                     g_cb + (size_t)(2 * NCODE + row) * DH + c16 * 8);
            }
            cp_commit();
        } else if (L == 1) {      // G hi/lo -> CB1
#pragma unroll
            for (int i = 0; i < 8; i++) {
                int g = i * 512 + t;
                int s = g >> 11, row = (g >> 4) & 127, c16 = g & 15;
                cp16(aCB1 + s * 34816 + row * 272 + c16 * 16,
                     g_G + (size_t)s * DH * DH + (size_t)row * DH + c16 * 8);
            }
            cp_commit();
        }
        if (t < 128) {
            float bv = bestv[t]; int bi = besti[t];
#pragma unroll
            for (int w = 1; w < 4; w++) {
                float ov = bestv[w * 128 + t]; int oi = besti[w * 128 + t];
                if (ov < bv || (ov == bv && oi < bi)) { bv = ov; bi = oi; }
            }
            besti[t] = bi;
            if (L < 2) idx01[L * 128 + t] = bi;
            g_used[L * NCODE + bi] = 1;
        }
        __syncthreads();
        // remainder update (fp32 gather); final level writes restored
        const float* cbg = cbs[L];
#pragma unroll
        for (int i = 0; i < 8; i++) {
            int r = wid * 8 + i;
            int ci = besti[r];
            float4 cv = *(const float4*)(cbg + (size_t)ci * DH + lane * 4);
            uint32_t p0 = *(uint32_t*)&sA[r * 136 + lane * 4];
            uint32_t p1 = *(uint32_t*)&sA[r * 136 + lane * 4 + 2];
            float o0, o1, o2, o3;
            bf2f(p0, o0, o1); bf2f(p1, o2, o3);
            float n0 = o0 - cv.x, n1 = o1 - cv.y, n2 = o2 - cv.z, n3 = o3 - cv.w;
            rql += n0 * n0 + n1 * n1 + n2 * n2 + n3 * n3;
            if (L < 2) {
                st_bf2(&sA[r * 136 + lane * 4],     n0, n1);
                st_bf2(&sA[r * 136 + lane * 4 + 2], n2, n3);
            } else {
                int i0 = idx01[r], i1 = idx01[128 + r];
                float4 a0 = *(const float4*)(cb0 + (size_t)i0 * DH + lane * 4);
                float4 a1 = *(const float4*)(cb1 + (size_t)i1 * DH + lane * 4);
                st_bf2(&sA[r * 136 + lane * 4],
                       a0.x + a1.x + cv.x, a0.y + a1.y + cv.y);
                st_bf2(&sA[r * 136 + lane * 4 + 2],
                       a0.z + a1.z + cv.z, a0.w + a1.w + cv.w);
            }
        }
    }

    // =========== Final: qsum = sum r G r^T, cross = sum r.U ===========
    cp_wait<0>();
    __syncthreads();              // restored + G visible
    float accR[2][4][4];
#pragma unroll
    for (int mt = 0; mt < 2; mt++)
#pragma unroll
        for (int nt = 0; nt < 4; nt++)
#pragma unroll
            for (int q = 0; q < 4; q++) accR[mt][nt][q] = 0.f;
#pragma unroll
    for (int g2 = 0; g2 < 2; g2++) {
        uint32_t gB = aCB1 + g2 * 34816;
#pragma unroll
        for (int kt = 0; kt < 8; kt++) {
            uint32_t af[2][4], bfr[2][4];
#pragma unroll
            for (int mt = 0; mt < 2; mt++)
                ldsm4(af[mt], aSA + (wr * 32 + mt * 16 + (lane & 15)) * 272
                              + kt * 32 + (lane >> 4) * 16);
#pragma unroll
            for (int np = 0; np < 2; np++) {
                int n = wc * 32 + np * 16 + (lane & 7) + ((lane >> 4) & 1) * 8;
                ldsm4(bfr[np], gB + n * 272 + kt * 32 + ((lane >> 3) & 1) * 16);
            }
#pragma unroll
            for (int mt = 0; mt < 2; mt++)
#pragma unroll
                for (int np = 0; np < 2; np++) {
                    mma16816(accR[mt][2 * np],     af[mt], &bfr[np][0]);
                    mma16816(accR[mt][2 * np + 1], af[mt], &bfr[np][2]);
                }
        }
    }
    float qsum = 0.f;
    uint32_t* sA32 = (uint32_t*)sA;
    uint32_t* sU32 = (uint32_t*)sU;
#pragma unroll
    for (int mt = 0; mt < 2; mt++)
#pragma unroll
        for (int nt = 0; nt < 4; nt++) {
            int row = wr * 32 + mt * 16 + (lane >> 2);
            int col = wc * 32 + nt * 8 + (lane & 3) * 2;
            float r0, r1, r2, r3;
            bf2f(sA32[row * 68 + (col >> 1)], r0, r1);
            bf2f(sA32[(row + 8) * 68 + (col >> 1)], r2, r3);
            qsum += accR[mt][nt][0] * r0 + accR[mt][nt][1] * r1
                  + accR[mt][nt][2] * r2 + accR[mt][nt][3] * r3;
        }
    float cross = 0.f;
#pragma unroll
    for (int i = 0; i < 16; i++) {
        int g = i * 512 + t;
        int row = g >> 6, cp = g & 63;
        float a0, a1, b0, b1;
        bf2f(sA32[row * 68 + cp], a0, a1);
        bf2f(sU32[row * 68 + cp], b0, b1);
        cross += a0 * b0 + a1 * b1;
    }

    // ---- reductions ----
#pragma unroll
    for (int off = 16; off > 0; off >>= 1) {
        rql   += __shfl_xor_sync(0xffffffffu, rql, off);
        se2   += __shfl_xor_sync(0xffffffffu, se2, off);
        qsum  += __shfl_xor_sync(0xffffffffu, qsum, off);
        cross += __shfl_xor_sync(0xffffffffu, cross, off);
    }
    if (lane == 0) {
        atomicAdd(&g_rq, (double)rql);
        atomicAdd(&g_recon, (double)qsum - 2.0 * (double)cross + (double)se2);
    }
}

// ---------------- finalize ----------------
__global__ void k_finalize(float* __restrict__ out, int out_size) {
    __shared__ int cnt[3];
    int t = threadIdx.x;
    if (t < 3) cnt[t] = 0;
    __syncthreads();
    if (t < 3 * NCODE) { if (g_used[t]) atomicAdd(&cnt[t / NCODE], 1); }
    __syncthreads();
    if (t == 0) {
        double recon = g_recon / ((double)NROWS * (double)D_IN);
        double rq    = (1.0 + BETA) * g_rq / ((double)NROWS * (double)DH);
        float rf = (float)recon, qf = (float)rq;
        if (out_size > 0) out[0] = rf + qf;
        if (out_size > 1) out[1] = rf;
        if (out_size > 2) out[2] = qf;
        if (out_size > 3) out[3] = (float)cnt[0];
        if (out_size > 4) out[4] = (float)cnt[1];
        if (out_size > 5) out[5] = (float)cnt[2];
    }
    for (int i = 6 + t; i < out_size; i += blockDim.x) out[i] = 0.f;
}

// ---------------- launch ----------------
extern "C" void kernel_launch(void* const* d_in, const int* in_sizes, int n_in,
                              void* d_out, int out_size) {
    const float* emb  = (const float*)d_in[0];
    const float* Wenc = (const float*)d_in[1];
    const float* Wdec = (const float*)d_in[2];
    const float* cb0  = (const float*)d_in[3];
    const float* cb1  = (const float*)d_in[4];
    const float* cb2  = (const float*)d_in[5];

    cudaFuncSetAttribute(k_fused, cudaFuncAttributeMaxDynamicSharedMemorySize, F_SMEM);

    k_init<<<1, 768>>>();
    k_norms<<<3, 256>>>(cb0, cb1, cb2);
    k_cvt<<<448, 256>>>(Wenc, Wdec, cb0, cb1, cb2);
    k_gram<<<128, 128>>>(Wdec);
    k_fused<<<NROWS / 128, 512, F_SMEM>>>(emb, cb0, cb1, cb2);
    k_finalize<<<1, 768>>>((float*)d_out, out_size);
}

// round 17
// speedup vs baseline: 1.2800x; 1.2075x over previous
#include <cuda_runtime.h>
#include <cuda_bf16.h>
#include <cstdint>

#define NROWS   131072
#define D_IN    512
#define DH      128
#define NCODE   256
#define BETA    0.25

// ---------------- scratch ----------------
__device__ __nv_bfloat16  g_wenc[(size_t)DH * D_IN];      // 128 x 512
__device__ __nv_bfloat16  g_wdec[(size_t)D_IN * DH];      // 512 x 128
__device__ __nv_bfloat16  g_cb[3 * NCODE * DH];           // 3 x 256 x 128
__device__ float          g_cn[3 * NCODE];
__device__ double g_rq;
__device__ double g_recon;
__device__ int    g_used[3 * NCODE];

// ---------------- helpers ----------------
__device__ __forceinline__ uint32_t s2u(const void* p) {
    uint32_t a;
    asm("{ .reg .u64 t; cvta.to.shared.u64 t, %1; cvt.u32.u64 %0, t; }" : "=r"(a) : "l"(p));
    return a;
}
__device__ __forceinline__ void ldsm4(uint32_t* r, uint32_t addr) {
    asm volatile("ldmatrix.sync.aligned.m8n8.x4.shared.b16 {%0,%1,%2,%3}, [%4];"
        : "=r"(r[0]), "=r"(r[1]), "=r"(r[2]), "=r"(r[3]) : "r"(addr));
}
__device__ __forceinline__ void mma16816(float* c, const uint32_t* a, const uint32_t* b) {
    asm volatile("mma.sync.aligned.m16n8k16.row.col.f32.bf16.bf16.f32 "
        "{%0,%1,%2,%3}, {%4,%5,%6,%7}, {%8,%9}, {%0,%1,%2,%3};"
        : "+f"(c[0]), "+f"(c[1]), "+f"(c[2]), "+f"(c[3])
        : "r"(a[0]), "r"(a[1]), "r"(a[2]), "r"(a[3]), "r"(b[0]), "r"(b[1]));
}
__device__ __forceinline__ void st_bf2(__nv_bfloat16* p, float a, float b) {
    __nv_bfloat162 v = __floats2bfloat162_rn(a, b);
    *(uint32_t*)p = *(uint32_t*)&v;
}
__device__ __forceinline__ uint32_t pack_bf2(float a, float b) {
    __nv_bfloat162 v = __floats2bfloat162_rn(a, b);
    return *(uint32_t*)&v;
}
__device__ __forceinline__ void cp16(uint32_t dst, const void* src) {
    asm volatile("cp.async.cg.shared.global [%0], [%1], 16;" :: "r"(dst), "l"(src));
}
__device__ __forceinline__ void cp_commit() {
    asm volatile("cp.async.commit_group;" ::: "memory");
}
template<int N> __device__ __forceinline__ void cp_wait() {
    asm volatile("cp.async.wait_group %0;" :: "n"(N) : "memory");
}

// ---------------- init / norms / convert ----------------
__global__ void k_init() {
    int t = threadIdx.x;
    if (t == 0) { g_rq = 0.0; g_recon = 0.0; }
    if (t < 3 * NCODE) g_used[t] = 0;
}
__global__ void k_norms(const float* __restrict__ cb0,
                        const float* __restrict__ cb1,
                        const float* __restrict__ cb2) {
    const float* cbs[3] = {cb0, cb1, cb2};
    const float* cb = cbs[blockIdx.x];
    int t = threadIdx.x;
    float s = 0.f;
#pragma unroll
    for (int q = 0; q < 32; q++) {
        float4 v = *(const float4*)(cb + (size_t)t * DH + q * 4);
        s += v.x * v.x + v.y * v.y + v.z * v.z + v.w * v.w;
    }
    g_cn[blockIdx.x * NCODE + t] = s;
}
__global__ void k_cvt(const float* __restrict__ we, const float* __restrict__ wd,
                      const float* __restrict__ c0, const float* __restrict__ c1,
                      const float* __restrict__ c2) {
    int i = blockIdx.x * 256 + threadIdx.x;
    const float* src; uint32_t* dst; int off;
    if (i < 32768)       { src = we; dst = (uint32_t*)g_wenc;         off = i; }
    else if (i < 65536)  { src = wd; dst = (uint32_t*)g_wdec;         off = i - 32768; }
    else if (i < 81920)  { src = c0; dst = (uint32_t*)g_cb;           off = i - 65536; }
    else if (i < 98304)  { src = c1; dst = (uint32_t*)g_cb + 16384;   off = i - 81920; }
    else                 { src = c2; dst = (uint32_t*)g_cb + 32768;   off = i - 98304; }
    float2 v = ((const float2*)src)[off];
    __nv_bfloat162 p = __floats2bfloat162_rn(v.x, v.y);
    dst[off] = *(uint32_t*)&p;
}

// =========================================================================
// Fused kernel, 128 rows/CTA, 256 thr (2 row-groups x 4 col-groups),
// warp tile 64x32, 2 CTAs/SM. One barrier per pipeline iteration.
// smem map (bytes):
//  sA (rem -> restored, bf16 128x136) @ 0       34816
//  RG @ 34816 (73728):
//     GEMM1: ebuf0 @+0, ebuf1 @+18432 (128x72 elem, 144B stride)
//            wbuf0 @+36864, wbuf1 @+55296 (128x72 elem)
//     RQ/recon: cbbuf0 @+0, cbbuf1 @+36864 (128x136 elem, 272B stride)
//  bestv f32[4][128] @ 108544 2048
//  besti i32[4][128] @ 110592 2048  (besti[0..127] doubles as final idx)
//  idx01 i32[2][128] @ 112640 1024
// total 113664 -> 2 CTAs/SM
// =========================================================================
#define F_SA   0
#define F_RG   34816
#define F_BV   108544
#define F_BI   110592
#define F_IDX  112640
#define F_SMEM 113664

__global__ __launch_bounds__(256, 2) void k_fused(const float* __restrict__ emb,
                                                  const float* __restrict__ cb0,
                                                  const float* __restrict__ cb1,
                                                  const float* __restrict__ cb2) {
    extern __shared__ char smc[];
    __nv_bfloat16* sA = (__nv_bfloat16*)(smc + F_SA);
    float* bestv = (float*)(smc + F_BV);
    int*   besti = (int*)(smc + F_BI);
    int*   idx01 = (int*)(smc + F_IDX);
    uint32_t aBase = s2u(smc);
    uint32_t aSA = aBase + F_SA, aRG = aBase + F_RG;
    uint32_t aE[2] = {aRG, aRG + 18432};
    uint32_t aW[2] = {aRG + 36864, aRG + 55296};
    uint32_t aCBB[2] = {aRG, aRG + 36864};

    int t = threadIdx.x, lane = t & 31, wid = t >> 5;
    int wr = wid >> 2, wc = wid & 3;
    int row0 = blockIdx.x * 128;

    // ---- pre-loop: wenc chunk0, emb chunk0 regs + stage, emb chunk1 regs ----
#pragma unroll
    for (int i = 0; i < 4; i++) {
        int q = i * 256 + t;
        int row = q >> 3, c16 = q & 7;
        cp16(aW[0] + row * 144 + c16 * 16, g_wenc + (size_t)row * D_IN + c16 * 8);
    }
    cp_commit();

    float4 pe4[4][2];
#pragma unroll
    for (int i = 0; i < 4; i++) {
        int s = i * 256 + t;
        int row = s >> 3, cb8 = s & 7;
        const float* p = emb + (size_t)(row0 + row) * D_IN + cb8 * 8;
        pe4[i][0] = *(const float4*)p;
        pe4[i][1] = *(const float4*)(p + 4);
    }
#pragma unroll
    for (int i = 0; i < 4; i++) {
        int s = i * 256 + t;
        int row = s >> 3, cb8 = s & 7;
        uint4 u;
        u.x = pack_bf2(pe4[i][0].x, pe4[i][0].y);
        u.y = pack_bf2(pe4[i][0].z, pe4[i][0].w);
        u.z = pack_bf2(pe4[i][1].x, pe4[i][1].y);
        u.w = pack_bf2(pe4[i][1].z, pe4[i][1].w);
        *(uint4*)(smc + F_RG + row * 144 + cb8 * 16) = u;
    }
#pragma unroll
    for (int i = 0; i < 4; i++) {
        int s = i * 256 + t;
        int row = s >> 3, cb8 = s & 7;
        const float* p = emb + (size_t)(row0 + row) * D_IN + 64 + cb8 * 8;
        pe4[i][0] = *(const float4*)p;
        pe4[i][1] = *(const float4*)(p + 4);
    }

    // =========== Phase 1: latent = emb @ Wenc^T ===========
    float acc1[4][4][4];
#pragma unroll
    for (int mt = 0; mt < 4; mt++)
#pragma unroll
        for (int nt = 0; nt < 4; nt++)
#pragma unroll
            for (int j = 0; j < 4; j++) acc1[mt][nt][j] = 0.f;

    for (int c = 0; c < 8; c++) {
        cp_wait<0>();
        __syncthreads();
        if (c < 7) {
#pragma unroll
            for (int i = 0; i < 4; i++) {
                int q = i * 256 + t;
                int row = q >> 3, c16 = q & 7;
                cp16(aW[(c + 1) & 1] + row * 144 + c16 * 16,
                     g_wenc + (size_t)row * D_IN + (c + 1) * 64 + c16 * 8);
            }
            cp_commit();
#pragma unroll
            for (int i = 0; i < 4; i++) {
                int s = i * 256 + t;
                int row = s >> 3, cb8 = s & 7;
                uint4 u;
                u.x = pack_bf2(pe4[i][0].x, pe4[i][0].y);
                u.y = pack_bf2(pe4[i][0].z, pe4[i][0].w);
                u.z = pack_bf2(pe4[i][1].x, pe4[i][1].y);
                u.w = pack_bf2(pe4[i][1].z, pe4[i][1].w);
                *(uint4*)(smc + F_RG + ((c + 1) & 1) * 18432 + row * 144 + cb8 * 16) = u;
            }
        }
        if (c < 6) {
#pragma unroll
            for (int i = 0; i < 4; i++) {
                int s = i * 256 + t;
                int row = s >> 3, cb8 = s & 7;
                const float* p = emb + (size_t)(row0 + row) * D_IN + (c + 2) * 64 + cb8 * 8;
                pe4[i][0] = *(const float4*)p;
                pe4[i][1] = *(const float4*)(p + 4);
            }
        }
        uint32_t aEc = aE[c & 1], aWc = aW[c & 1];
#pragma unroll
        for (int kt = 0; kt < 4; kt++) {
            uint32_t af[4][4], bfr[2][4];
#pragma unroll
            for (int mt = 0; mt < 4; mt++)
                ldsm4(af[mt], aEc + ((wr * 64 + mt * 16 + (lane & 15)) * 72
                                     + kt * 16 + (lane >> 4) * 8) * 2);
#pragma unroll
            for (int np = 0; np < 2; np++) {
                int n = wc * 32 + np * 16 + (lane & 7) + ((lane >> 4) & 1) * 8;
                ldsm4(bfr[np], aWc + (n * 72 + kt * 16 + ((lane >> 3) & 1) * 8) * 2);
            }
#pragma unroll
            for (int mt = 0; mt < 4; mt++)
#pragma unroll
                for (int np = 0; np < 2; np++) {
                    mma16816(acc1[mt][2 * np],     af[mt], &bfr[np][0]);
                    mma16816(acc1[mt][2 * np + 1], af[mt], &bfr[np][2]);
                }
        }
    }
    __syncthreads();
#pragma unroll
    for (int mt = 0; mt < 4; mt++)
#pragma unroll
        for (int nt = 0; nt < 4; nt++) {
            int row = wr * 64 + mt * 16 + (lane >> 2);
            int col = wc * 32 + nt * 8 + (lane & 3) * 2;
            st_bf2(&sA[row * 136 + col],       acc1[mt][nt][0], acc1[mt][nt][1]);
            st_bf2(&sA[(row + 8) * 136 + col], acc1[mt][nt][2], acc1[mt][nt][3]);
        }
#pragma unroll
    for (int i = 0; i < 8; i++) {
        int q = i * 256 + t;
        int row = q >> 4, c16 = q & 15;
        cp16(aCBB[0] + row * 272 + c16 * 16, g_cb + (size_t)row * DH + c16 * 8);
    }
    cp_commit();

    // =========== Phase 2: 3-level RQ, 128-code slabs ===========
    float rql = 0.f;
    const float* cbs[3] = {cb0, cb1, cb2};
    float best[8]; int bidx[8];

    for (int j = 0; j < 6; j++) {
        int L = j >> 1, h = j & 1;
        uint32_t aCBc = aCBB[j & 1];
        cp_wait<0>();
        __syncthreads();
        if (j < 5) {
#pragma unroll
            for (int i = 0; i < 8; i++) {
                int q = i * 256 + t;
                int row = q >> 4, c16 = q & 15;
                cp16(aCBB[(j + 1) & 1] + row * 272 + c16 * 16,
                     g_cb + (size_t)((j + 1) >> 1) * NCODE * DH
                          + (size_t)(((j + 1) & 1) * 128 + row) * DH + c16 * 8);
            }
            cp_commit();
        } else {
#pragma unroll
            for (int i = 0; i < 8; i++) {
                int q = i * 256 + t;
                int row = q >> 4, c16 = q & 15;
                cp16(aCBB[0] + row * 272 + c16 * 16, g_wdec + (size_t)row * DH + c16 * 8);
            }
            cp_commit();
        }
        if (h == 0) {
#pragma unroll
            for (int s = 0; s < 8; s++) { best[s] = 3.4e38f; bidx[s] = 0; }
        }
        float2 cnv[4];
#pragma unroll
        for (int nt = 0; nt < 4; nt++)
            cnv[nt] = *(const float2*)(g_cn + L * NCODE + h * 128 + wc * 32
                                       + nt * 8 + (lane & 3) * 2);

        float acc[4][4][4];
#pragma unroll
        for (int mt = 0; mt < 4; mt++)
#pragma unroll
            for (int nt = 0; nt < 4; nt++)
#pragma unroll
                for (int q = 0; q < 4; q++) acc[mt][nt][q] = 0.f;
#pragma unroll
        for (int kt = 0; kt < 8; kt++) {
            uint32_t af[4][4], bfr[2][4];
#pragma unroll
            for (int mt = 0; mt < 4; mt++)
                ldsm4(af[mt], aSA + ((wr * 64 + mt * 16 + (lane & 15)) * 136
                                     + kt * 16 + (lane >> 4) * 8) * 2);
#pragma unroll
            for (int np = 0; np < 2; np++) {
                int n = wc * 32 + np * 16 + (lane & 7) + ((lane >> 4) & 1) * 8;
                ldsm4(bfr[np], aCBc + (n * 136 + kt * 16 + ((lane >> 3) & 1) * 8) * 2);
            }
#pragma unroll
            for (int mt = 0; mt < 4; mt++)
#pragma unroll
                for (int np = 0; np < 2; np++) {
                    mma16816(acc[mt][2 * np],     af[mt], &bfr[np][0]);
                    mma16816(acc[mt][2 * np + 1], af[mt], &bfr[np][2]);
                }
        }
#pragma unroll
        for (int mt = 0; mt < 4; mt++)
#pragma unroll
            for (int nt = 0; nt < 4; nt++) {
                int col = h * 128 + wc * 32 + nt * 8 + (lane & 3) * 2;
#pragma unroll
                for (int hi = 0; hi < 2; hi++) {
                    int s = mt * 2 + hi;
                    float k0 = fmaf(-2.f, acc[mt][nt][hi * 2],     cnv[nt].x);
                    float k1 = fmaf(-2.f, acc[mt][nt][hi * 2 + 1], cnv[nt].y);
                    if (k0 < best[s]) { best[s] = k0; bidx[s] = col; }
                    if (k1 < best[s]) { best[s] = k1; bidx[s] = col + 1; }
                }
            }

        if (h == 1) {
            const float* cbg = cbs[L];
#pragma unroll
            for (int s = 0; s < 8; s++) {
                float bv = best[s]; int bi = bidx[s];
#pragma unroll
                for (int off = 1; off < 4; off <<= 1) {
                    float ov = __shfl_xor_sync(0xffffffffu, bv, off);
                    int   oi = __shfl_xor_sync(0xffffffffu, bi, off);
                    if (ov < bv || (ov == bv && oi < bi)) { bv = ov; bi = oi; }
                }
                if ((lane & 3) == 0) {
                    int row = wr * 64 + (s >> 1) * 16 + (s & 1) * 8 + (lane >> 2);
                    bestv[wc * 128 + row] = bv;
                    besti[wc * 128 + row] = bi;
                }
            }
            __syncthreads();
            if (t < 128) {
                float bv = bestv[t]; int bi = besti[t];
#pragma unroll
                for (int w = 1; w < 4; w++) {
                    float ov = bestv[w * 128 + t]; int oi = besti[w * 128 + t];
                    if (ov < bv || (ov == bv && oi < bi)) { bv = ov; bi = oi; }
                }
                besti[t] = bi;
                if (L < 2) idx01[L * 128 + t] = bi;
                g_used[L * NCODE + bi] = 1;
            }
            __syncthreads();
            // remainder update, batched gathers (MLP=4)
#pragma unroll
            for (int ib = 0; ib < 4; ib++) {
                int cis[4]; float4 cvs[4];
#pragma unroll
                for (int k = 0; k < 4; k++)
                    cis[k] = besti[wid * 16 + ib * 4 + k];
#pragma unroll
                for (int k = 0; k < 4; k++)
                    cvs[k] = *(const float4*)(cbg + (size_t)cis[k] * DH + lane * 4);
#pragma unroll
                for (int k = 0; k < 4; k++) {
                    int r = wid * 16 + ib * 4 + k;
                    float4 cv = cvs[k];
                    uint32_t p0 = *(uint32_t*)&sA[r * 136 + lane * 4];
                    uint32_t p1 = *(uint32_t*)&sA[r * 136 + lane * 4 + 2];
                    __nv_bfloat162 b0 = *(__nv_bfloat162*)&p0;
                    __nv_bfloat162 b1 = *(__nv_bfloat162*)&p1;
                    float n0 = __low2float(b0)  - cv.x;
                    float n1 = __high2float(b0) - cv.y;
                    float n2 = __low2float(b1)  - cv.z;
                    float n3 = __high2float(b1) - cv.w;
                    rql += n0 * n0 + n1 * n1 + n2 * n2 + n3 * n3;
                    if (L < 2) {
                        st_bf2(&sA[r * 136 + lane * 4],     n0, n1);
                        st_bf2(&sA[r * 136 + lane * 4 + 2], n2, n3);
                    } else {
                        int i0 = idx01[r], i1 = idx01[128 + r];
                        float4 a0 = *(const float4*)(cb0 + (size_t)i0 * DH + lane * 4);
                        float4 a1 = *(const float4*)(cb1 + (size_t)i1 * DH + lane * 4);
                        st_bf2(&sA[r * 136 + lane * 4],
                               a0.x + a1.x + cv.x, a0.y + a1.y + cv.y);
                        st_bf2(&sA[r * 136 + lane * 4 + 2],
                               a0.z + a1.z + cv.z, a0.w + a1.w + cv.w);
                    }
                }
            }
        }
    }

    // =========== Phase 3: recon GEMM + fused MSE (4 passes of 128 N) =======
    float local = 0.f;
    for (int p = 0; p < 4; p++) {
        uint32_t aDc = aCBB[p & 1];
        cp_wait<0>();
        __syncthreads();
        if (p < 3) {
#pragma unroll
            for (int i = 0; i < 8; i++) {
                int q = i * 256 + t;
                int row = q >> 4, c16 = q & 15;
                cp16(aCBB[(p + 1) & 1] + row * 272 + c16 * 16,
                     g_wdec + (size_t)((p + 1) * 128 + row) * DH + c16 * 8);
            }
            cp_commit();
        }
        float accR[4][4][4];
#pragma unroll
        for (int mt = 0; mt < 4; mt++)
#pragma unroll
            for (int nt = 0; nt < 4; nt++)
#pragma unroll
                for (int q = 0; q < 4; q++) accR[mt][nt][q] = 0.f;
#pragma unroll
        for (int kt = 0; kt < 8; kt++) {
            uint32_t af[4][4], bfr[2][4];
#pragma unroll
            for (int mt = 0; mt < 4; mt++)
                ldsm4(af[mt], aSA + ((wr * 64 + mt * 16 + (lane & 15)) * 136
                                     + kt * 16 + (lane >> 4) * 8) * 2);
#pragma unroll
            for (int np = 0; np < 2; np++) {
                int n = wc * 32 + np * 16 + (lane & 7) + ((lane >> 4) & 1) * 8;
                ldsm4(bfr[np], aDc + (n * 136 + kt * 16 + ((lane >> 3) & 1) * 8) * 2);
            }
#pragma unroll
            for (int mt = 0; mt < 4; mt++)
#pragma unroll
                for (int np = 0; np < 2; np++) {
                    mma16816(accR[mt][2 * np],     af[mt], &bfr[np][0]);
                    mma16816(accR[mt][2 * np + 1], af[mt], &bfr[np][2]);
                }
        }
        // epilogue: batched emb loads per mt (MLP=8), consumed immediately
#pragma unroll
        for (int mt = 0; mt < 4; mt++) {
            float2 e[8];
            int row = row0 + wr * 64 + mt * 16 + (lane >> 2);
#pragma unroll
            for (int nt = 0; nt < 4; nt++) {
                int col = p * 128 + wc * 32 + nt * 8 + (lane & 3) * 2;
                e[nt * 2]     = *(const float2*)(emb + (size_t)row * D_IN + col);
                e[nt * 2 + 1] = *(const float2*)(emb + (size_t)(row + 8) * D_IN + col);
            }
#pragma unroll
            for (int nt = 0; nt < 4; nt++) {
                float d0 = accR[mt][nt][0] - e[nt * 2].x;
                float d1 = accR[mt][nt][1] - e[nt * 2].y;
                float d2 = accR[mt][nt][2] - e[nt * 2 + 1].x;
                float d3 = accR[mt][nt][3] - e[nt * 2 + 1].y;
                local += d0 * d0 + d1 * d1 + d2 * d2 + d3 * d3;
            }
        }
    }

    // ---- reductions ----
#pragma unroll
    for (int off = 16; off > 0; off >>= 1) {
        rql   += __shfl_xor_sync(0xffffffffu, rql, off);
        local += __shfl_xor_sync(0xffffffffu, local, off);
    }
    if (lane == 0) {
        atomicAdd(&g_rq, (double)rql);
        atomicAdd(&g_recon, (double)local);
    }
}

// ---------------- finalize ----------------
__global__ void k_finalize(float* __restrict__ out, int out_size) {
    __shared__ int cnt[3];
    int t = threadIdx.x;
    if (t < 3) cnt[t] = 0;
    __syncthreads();
    if (t < 3 * NCODE) { if (g_used[t]) atomicAdd(&cnt[t / NCODE], 1); }
    __syncthreads();
    if (t == 0) {
        double recon = g_recon / ((double)NROWS * (double)D_IN);
        double rq    = (1.0 + BETA) * g_rq / ((double)NROWS * (double)DH);
        float rf = (float)recon, qf = (float)rq;
        if (out_size > 0) out[0] = rf + qf;
        if (out_size > 1) out[1] = rf;
        if (out_size > 2) out[2] = qf;
        if (out_size > 3) out[3] = (float)cnt[0];
        if (out_size > 4) out[4] = (float)cnt[1];
        if (out_size > 5) out[5] = (float)cnt[2];
    }
    for (int i = 6 + t; i < out_size; i += blockDim.x) out[i] = 0.f;
}

// ---------------- launch ----------------
extern "C" void kernel_launch(void* const* d_in, const int* in_sizes, int n_in,
                              void* d_out, int out_size) {
    const float* emb  = (const float*)d_in[0];
    const float* Wenc = (const float*)d_in[1];
    const float* Wdec = (const float*)d_in[2];
    const float* cb0  = (const float*)d_in[3];
    const float* cb1  = (const float*)d_in[4];
    const float* cb2  = (const float*)d_in[5];

    cudaFuncSetAttribute(k_fused, cudaFuncAttributeMaxDynamicSharedMemorySize, F_SMEM);

    k_init<<<1, 768>>>();
    k_norms<<<3, 256>>>(cb0, cb1, cb2);
    k_cvt<<<448, 256>>>(Wenc, Wdec, cb0, cb1, cb2);
    k_fused<<<NROWS / 128, 256, F_SMEM>>>(emb, cb0, cb1, cb2);
    k_finalize<<<1, 768>>>((float*)d_out, out_size);
}